// round 3
// baseline (speedup 1.0000x reference)
#include <cuda_runtime.h>
#include <cstdint>

#define NROWS 384
#define DDIM  768

// Scratch for the two small GEMM outputs (A has b1 folded in).
__device__ float g_A[NROWS * DDIM];
__device__ float g_B[NROWS * DDIM];

// ---------------------------------------------------------------------------
// Phase 1: C = P @ Wt^T for the concatenated 1536 output columns.
//   col jj <  768 : g_A[i][jj] = sum_k P[i,k] * W1[jj,     k] + b1[jj]
//   col jj >= 768 : g_B[i][jj'] = sum_k P[i,k] * W1[jj',768+k]
// Tiled fp32 SIMT GEMM: BM=64, BN=32, BK=16, 256 threads, 4x2 per thread.
// Grid: (1536/32, 384/64) = (48, 6) = 288 CTAs -> 2 CTAs/SM, 16 warps/SM.
// ---------------------------------------------------------------------------
__global__ void gemm_kernel(const float* __restrict__ P,
                            const float* __restrict__ W1,
                            const float* __restrict__ b1) {
    __shared__ float Ps[16][68];   // [k][i], 64 i cols + pad
    __shared__ float Qs[16][36];   // [k][j], 32 j cols + pad

    const int t  = threadIdx.x;        // 0..255
    const int tx = t & 15;             // j micro-tile (2 j's)
    const int ty = t >> 4;             // i micro-tile (4 i's)
    const int col0 = blockIdx.x * 32;  // 0..1504
    const int row0 = blockIdx.y * 64;
    const bool isB = (col0 >= DDIM);
    const float* Wbase = W1 + (isB ? (size_t)(col0 - DDIM) * (2 * DDIM) + DDIM
                                   : (size_t)col0 * (2 * DDIM));

    // P-tile load mapping: 64 rows x 16 k = 256 float4, one per thread.
    const int plr  = t >> 2;           // 0..63
    const int plc4 = (t & 3) << 2;     // 0,4,8,12
    // W-tile load mapping: 32 rows x 16 k = 128 float4, threads 0..127.
    const int wlr  = t >> 2;           // 0..31 for t<128
    const int wlc4 = (t & 3) << 2;

    float acc[4][2];
#pragma unroll
    for (int a = 0; a < 4; a++) { acc[a][0] = 0.f; acc[a][1] = 0.f; }

    for (int k0 = 0; k0 < DDIM; k0 += 16) {
        float4 pv = *(const float4*)(P + (size_t)(row0 + plr) * DDIM + k0 + plc4);
        Ps[plc4 + 0][plr] = pv.x; Ps[plc4 + 1][plr] = pv.y;
        Ps[plc4 + 2][plr] = pv.z; Ps[plc4 + 3][plr] = pv.w;
        if (t < 128) {
            float4 wv = *(const float4*)(Wbase + (size_t)wlr * (2 * DDIM) + k0 + wlc4);
            Qs[wlc4 + 0][wlr] = wv.x; Qs[wlc4 + 1][wlr] = wv.y;
            Qs[wlc4 + 2][wlr] = wv.z; Qs[wlc4 + 3][wlr] = wv.w;
        }
        __syncthreads();

#pragma unroll
        for (int k = 0; k < 16; k++) {
            float4 av = *(const float4*)&Ps[k][ty << 2];
            float2 bv = *(const float2*)&Qs[k][tx << 1];
            float aa[4] = {av.x, av.y, av.z, av.w};
#pragma unroll
            for (int a = 0; a < 4; a++) {
                acc[a][0] = fmaf(aa[a], bv.x, acc[a][0]);
                acc[a][1] = fmaf(aa[a], bv.y, acc[a][1]);
            }
        }
        __syncthreads();
    }

    const int cbase = isB ? (col0 - DDIM) : col0;
    float* dst = isB ? g_B : g_A;
#pragma unroll
    for (int a = 0; a < 4; a++) {
        const int i = row0 + (ty << 2) + a;
#pragma unroll
        for (int b = 0; b < 2; b++) {
            const int j = cbase + (tx << 1) + b;
            float v = acc[a][b];
            if (!isB) v += b1[j];
            dst[(size_t)i * DDIM + j] = v;
        }
    }
}

// ---------------------------------------------------------------------------
// Phase 2: fused  out[i,j,c] = sum_d tanh(g_A[i,d] + g_B[j,d]) * W2[c,d] + b2[c]
// CTA tile: 16 i x 32 j, 256 threads. tx=0..15 -> j = tx + 16*jj (jj=0,1),
// ty=0..15 -> i. d processed in smem chunks of 64, vectorized float2 over dk.
// Row stride SP=70: 70 mod 32 = 6, 6*tx distinct for tx=0..15 -> LDS.64
// conflict-free. Grid (12, 24) = 288 CTAs -> 2 CTAs/SM, occ 25%.
// MUFU.TANH-bound: floor ~24us.
// ---------------------------------------------------------------------------
#define TI 16
#define TJ 32
#define SP 70

__global__ void pair_kernel(const float* __restrict__ W2,
                            const float* __restrict__ b2,
                            float* __restrict__ out) {
    __shared__ float As[TI * SP];
    __shared__ float Bs[TJ * SP];
    __shared__ float W0s[64];
    __shared__ float W1s[64];

    const int t  = threadIdx.x;   // 0..255
    const int tx = t & 15;
    const int ty = t >> 4;
    const int i0 = blockIdx.y * TI;
    const int j0 = blockIdx.x * TJ;

    float acc0[2] = {0.f, 0.f};
    float acc1[2] = {0.f, 0.f};

    for (int d0 = 0; d0 < DDIM; d0 += 64) {
        // Fill As: 16x64 floats = 256 float4 -> 1 per thread (two f2 stores,
        // SP=70 rows are only 8B-aligned).
        {
            const int row = t >> 4, c4 = (t & 15) << 2;
            float4 v = *(const float4*)(g_A + (size_t)(i0 + row) * DDIM + d0 + c4);
            *(float2*)&As[row * SP + c4]     = make_float2(v.x, v.y);
            *(float2*)&As[row * SP + c4 + 2] = make_float2(v.z, v.w);
        }
        // Fill Bs: 32x64 floats = 512 float4 -> 2 per thread.
#pragma unroll
        for (int r = 0; r < 2; r++) {
            const int f = t + 256 * r;
            const int row = f >> 4, c4 = (f & 15) << 2;
            float4 v = *(const float4*)(g_B + (size_t)(j0 + row) * DDIM + d0 + c4);
            *(float2*)&Bs[row * SP + c4]     = make_float2(v.x, v.y);
            *(float2*)&Bs[row * SP + c4 + 2] = make_float2(v.z, v.w);
        }
        // Fill W2 chunk (2 x 64).
        if (t < 16) {
            const int c4 = t << 2;
            *(float4*)&W0s[c4] = *(const float4*)(W2 + d0 + c4);
        } else if (t < 32) {
            const int c4 = (t - 16) << 2;
            *(float4*)&W1s[c4] = *(const float4*)(W2 + DDIM + d0 + c4);
        }
        __syncthreads();

        const float* Arow = &As[ty * SP];
        const float* Brow0 = &Bs[tx * SP];
        const float* Brow1 = &Bs[(tx + 16) * SP];

#pragma unroll
        for (int dk = 0; dk < 64; dk += 2) {
            const float2 a2  = *(const float2*)&Arow[dk];
            const float2 w02 = *(const float2*)&W0s[dk];
            const float2 w12 = *(const float2*)&W1s[dk];

            {   // jj = 0
                const float2 b2v = *(const float2*)&Brow0[dk];
                float th0, th1;
                asm("tanh.approx.f32 %0, %1;" : "=f"(th0) : "f"(a2.x + b2v.x));
                asm("tanh.approx.f32 %0, %1;" : "=f"(th1) : "f"(a2.y + b2v.y));
                acc0[0] = fmaf(th0, w02.x, acc0[0]);
                acc0[0] = fmaf(th1, w02.y, acc0[0]);
                acc1[0] = fmaf(th0, w12.x, acc1[0]);
                acc1[0] = fmaf(th1, w12.y, acc1[0]);
            }
            {   // jj = 1
                const float2 b2v = *(const float2*)&Brow1[dk];
                float th0, th1;
                asm("tanh.approx.f32 %0, %1;" : "=f"(th0) : "f"(a2.x + b2v.x));
                asm("tanh.approx.f32 %0, %1;" : "=f"(th1) : "f"(a2.y + b2v.y));
                acc0[1] = fmaf(th0, w02.x, acc0[1]);
                acc0[1] = fmaf(th1, w02.y, acc0[1]);
                acc1[1] = fmaf(th0, w12.x, acc1[1]);
                acc1[1] = fmaf(th1, w12.y, acc1[1]);
            }
        }
        __syncthreads();
    }

    const float bb0 = b2[0];
    const float bb1 = b2[1];
    const int i = i0 + ty;
#pragma unroll
    for (int jj = 0; jj < 2; jj++) {
        const int j = j0 + tx + 16 * jj;
        float2 v = make_float2(acc0[jj] + bb0, acc1[jj] + bb1);
        *(float2*)(out + ((size_t)i * NROWS + j) * 2) = v;
    }
}

// ---------------------------------------------------------------------------
extern "C" void kernel_launch(void* const* d_in, const int* in_sizes, int n_in,
                              void* d_out, int out_size) {
    const float* P  = (const float*)d_in[0];   // [384, 768]
    const float* W1 = (const float*)d_in[1];   // [768, 1536]
    const float* b1 = (const float*)d_in[2];   // [768]
    const float* W2 = (const float*)d_in[3];   // [2, 768]
    const float* b2 = (const float*)d_in[4];   // [2]
    float* out = (float*)d_out;                // [384, 384, 2]

    gemm_kernel<<<dim3(48, 6), 256>>>(P, W1, b1);
    pair_kernel<<<dim3(12, 24), 256>>>(W2, b2, out);
}

// round 4
// speedup vs baseline: 1.6477x; 1.6477x over previous
#include <cuda_runtime.h>
#include <cstdint>

#define NROWS 384
#define DDIM  768

// Scratch for the two small GEMM outputs (A has b1 folded in).
__device__ float g_A[NROWS * DDIM];
__device__ float g_B[NROWS * DDIM];

// ---------------------------------------------------------------------------
// Phase 1 (round-2 version, measured ~32us): C = P @ W1half^T.
// Tiled fp32 SIMT GEMM: BM=BN=64, BK=16, 256 threads, 4x4 per thread.
// Grid: (1536/64, 384/64) = (24, 6) = 144 CTAs.
// ---------------------------------------------------------------------------
__global__ void gemm_kernel(const float* __restrict__ P,
                            const float* __restrict__ W1,
                            const float* __restrict__ b1) {
    __shared__ float Ps[16][68];   // [k][i]
    __shared__ float Qs[16][68];   // [k][j]

    const int t  = threadIdx.x;        // 0..255
    const int tx = t & 15;
    const int ty = t >> 4;
    const int col0 = blockIdx.x * 64;
    const int row0 = blockIdx.y * 64;
    const bool isB = (col0 >= DDIM);
    const float* Wbase = W1 + (isB ? (size_t)(col0 - DDIM) * (2 * DDIM) + DDIM
                                   : (size_t)col0 * (2 * DDIM));

    const int lr  = t >> 2;            // 0..63
    const int lc4 = (t & 3) << 2;      // 0,4,8,12

    float acc[4][4];
#pragma unroll
    for (int a = 0; a < 4; a++)
#pragma unroll
        for (int b = 0; b < 4; b++) acc[a][b] = 0.0f;

    for (int k0 = 0; k0 < DDIM; k0 += 16) {
        float4 pv = *(const float4*)(P + (size_t)(row0 + lr) * DDIM + k0 + lc4);
        Ps[lc4 + 0][lr] = pv.x; Ps[lc4 + 1][lr] = pv.y;
        Ps[lc4 + 2][lr] = pv.z; Ps[lc4 + 3][lr] = pv.w;
        float4 wv = *(const float4*)(Wbase + (size_t)lr * (2 * DDIM) + k0 + lc4);
        Qs[lc4 + 0][lr] = wv.x; Qs[lc4 + 1][lr] = wv.y;
        Qs[lc4 + 2][lr] = wv.z; Qs[lc4 + 3][lr] = wv.w;
        __syncthreads();

#pragma unroll
        for (int k = 0; k < 16; k++) {
            float4 av = *(const float4*)&Ps[k][ty << 2];
            float4 bv = *(const float4*)&Qs[k][tx << 2];
            float aa[4] = {av.x, av.y, av.z, av.w};
            float bb[4] = {bv.x, bv.y, bv.z, bv.w};
#pragma unroll
            for (int a = 0; a < 4; a++)
#pragma unroll
                for (int b = 0; b < 4; b++)
                    acc[a][b] = fmaf(aa[a], bb[b], acc[a][b]);
        }
        __syncthreads();
    }

    const int cbase = isB ? (col0 - DDIM) : col0;
    float* dst = isB ? g_B : g_A;
#pragma unroll
    for (int a = 0; a < 4; a++) {
        const int i = row0 + (ty << 2) + a;
#pragma unroll
        for (int b = 0; b < 4; b++) {
            const int j = cbase + (tx << 2) + b;
            float v = acc[a][b];
            if (!isB) v += b1[j];
            dst[(size_t)i * DDIM + j] = v;
        }
    }
}

// ---------------------------------------------------------------------------
// Phase 2: fused  out[i,j,c] = sum_d tanh(g_A[i,d] + g_B[j,d]) * W2[c,d] + b2[c]
// CTA tile: 16 i x 32 j, 512 threads. tz = t>>8 splits d in half (384 each);
// within a half: tx=0..15 -> j = tx + 16*jj, ty=0..15 -> i.
// d processed in smem chunks of 64 per half, float2-vectorized over dk.
// Row stride SP=70 (6*tx mod 32 distinct for tx=0..15 -> LDS.64 conflict-free).
// Grid (12, 24) = 288 CTAs x 16 warps -> 2 CTAs/SM, 32 warps/SM, 8/SMSP.
// Cross-half reduction through smem at the end. MUFU.TANH floor ~24us.
// ---------------------------------------------------------------------------
#define TI 16
#define TJ 32
#define SP 70
#define DHALF 384

__global__ void __launch_bounds__(512, 2)
pair_kernel(const float* __restrict__ W2,
            const float* __restrict__ b2,
            float* __restrict__ out) {
    __shared__ float As[2][TI * SP];
    __shared__ float Bs[2][TJ * SP];
    __shared__ float W0s[2][64];
    __shared__ float W1s[2][64];
    __shared__ float Red[256 * 4];

    const int t  = threadIdx.x;   // 0..511
    const int tz = t >> 8;        // d-half
    const int tt = t & 255;
    const int tx = tt & 15;
    const int ty = tt >> 4;
    const int i0 = blockIdx.y * TI;
    const int j0 = blockIdx.x * TJ;

    float acc0[2] = {0.f, 0.f};
    float acc1[2] = {0.f, 0.f};

    float* Ash = As[tz];
    float* Bsh = Bs[tz];
    float* W0h = W0s[tz];
    float* W1h = W1s[tz];

    for (int c = 0; c < DHALF / 64; c++) {
        const int d0 = tz * DHALF + c * 64;
        // Fill As half: 16x64 floats = 256 float4 -> 1 per half-thread.
        {
            const int row = tt >> 4, c4 = (tt & 15) << 2;
            float4 v = *(const float4*)(g_A + (size_t)(i0 + row) * DDIM + d0 + c4);
            *(float2*)&Ash[row * SP + c4]     = make_float2(v.x, v.y);
            *(float2*)&Ash[row * SP + c4 + 2] = make_float2(v.z, v.w);
        }
        // Fill Bs half: 32x64 floats = 512 float4 -> 2 per half-thread.
#pragma unroll
        for (int r = 0; r < 2; r++) {
            const int f = tt + 256 * r;
            const int row = f >> 4, c4 = (f & 15) << 2;
            float4 v = *(const float4*)(g_B + (size_t)(j0 + row) * DDIM + d0 + c4);
            *(float2*)&Bsh[row * SP + c4]     = make_float2(v.x, v.y);
            *(float2*)&Bsh[row * SP + c4 + 2] = make_float2(v.z, v.w);
        }
        // Fill W2 chunk (2 x 64) for this half.
        if (tt < 16) {
            const int c4 = tt << 2;
            *(float4*)&W0h[c4] = *(const float4*)(W2 + d0 + c4);
        } else if (tt < 32) {
            const int c4 = (tt - 16) << 2;
            *(float4*)&W1h[c4] = *(const float4*)(W2 + DDIM + d0 + c4);
        }
        __syncthreads();

        const float* Arow  = &Ash[ty * SP];
        const float* Brow0 = &Bsh[tx * SP];
        const float* Brow1 = &Bsh[(tx + 16) * SP];

#pragma unroll 8
        for (int dk = 0; dk < 64; dk += 2) {
            const float2 a2  = *(const float2*)&Arow[dk];
            const float2 w02 = *(const float2*)&W0h[dk];
            const float2 w12 = *(const float2*)&W1h[dk];

            {   // jj = 0
                const float2 bv = *(const float2*)&Brow0[dk];
                float th0, th1;
                asm("tanh.approx.f32 %0, %1;" : "=f"(th0) : "f"(a2.x + bv.x));
                asm("tanh.approx.f32 %0, %1;" : "=f"(th1) : "f"(a2.y + bv.y));
                acc0[0] = fmaf(th0, w02.x, acc0[0]);
                acc0[0] = fmaf(th1, w02.y, acc0[0]);
                acc1[0] = fmaf(th0, w12.x, acc1[0]);
                acc1[0] = fmaf(th1, w12.y, acc1[0]);
            }
            {   // jj = 1
                const float2 bv = *(const float2*)&Brow1[dk];
                float th0, th1;
                asm("tanh.approx.f32 %0, %1;" : "=f"(th0) : "f"(a2.x + bv.x));
                asm("tanh.approx.f32 %0, %1;" : "=f"(th1) : "f"(a2.y + bv.y));
                acc0[1] = fmaf(th0, w02.x, acc0[1]);
                acc0[1] = fmaf(th1, w02.y, acc0[1]);
                acc1[1] = fmaf(th0, w12.x, acc1[1]);
                acc1[1] = fmaf(th1, w12.y, acc1[1]);
            }
        }
        __syncthreads();
    }

    // Cross-half reduction: tz=1 parks its partials in smem, tz=0 combines.
    if (tz == 1) {
        float4 v = make_float4(acc0[0], acc0[1], acc1[0], acc1[1]);
        *(float4*)&Red[tt * 4] = v;
    }
    __syncthreads();
    if (tz == 0) {
        float4 v = *(const float4*)&Red[tt * 4];
        const float bb0 = b2[0];
        const float bb1 = b2[1];
        const int i = i0 + ty;
        {
            const int j = j0 + tx;
            float2 o = make_float2(acc0[0] + v.x + bb0, acc1[0] + v.z + bb1);
            *(float2*)(out + ((size_t)i * NROWS + j) * 2) = o;
        }
        {
            const int j = j0 + tx + 16;
            float2 o = make_float2(acc0[1] + v.y + bb0, acc1[1] + v.w + bb1);
            *(float2*)(out + ((size_t)i * NROWS + j) * 2) = o;
        }
    }
}

// ---------------------------------------------------------------------------
extern "C" void kernel_launch(void* const* d_in, const int* in_sizes, int n_in,
                              void* d_out, int out_size) {
    const float* P  = (const float*)d_in[0];   // [384, 768]
    const float* W1 = (const float*)d_in[1];   // [768, 1536]
    const float* b1 = (const float*)d_in[2];   // [768]
    const float* W2 = (const float*)d_in[3];   // [2, 768]
    const float* b2 = (const float*)d_in[4];   // [2]
    float* out = (float*)d_out;                // [384, 384, 2]

    gemm_kernel<<<dim3(24, 6), 256>>>(P, W1, b1);
    pair_kernel<<<dim3(12, 24), 512>>>(W2, b2, out);
}

// round 5
// speedup vs baseline: 1.9359x; 1.1750x over previous
#include <cuda_runtime.h>
#include <cstdint>

#define NROWS 384
#define DDIM  768

// Scratch for the two small GEMM outputs (A has b1 folded in).
__device__ float g_A[NROWS * DDIM];
__device__ float g_B[NROWS * DDIM];

// ---------------------------------------------------------------------------
// Phase 1: C = P @ W1half^T (concat columns: first 768 -> g_A (+b1), rest -> g_B).
// Tiled fp32 SIMT GEMM: BM=BN=64, BK=16, 256 threads, 4x4 per thread.
// Register-prefetch pipeline: LDG chunk c+1 while computing chunk c, so the
// ~260cyc L2 latency hides under the ~580cyc compute phase.
// Grid: (1536/64, 384/64) = (24, 6) = 144 CTAs.
// ---------------------------------------------------------------------------
__global__ void __launch_bounds__(256)
gemm_kernel(const float* __restrict__ P,
            const float* __restrict__ W1,
            const float* __restrict__ b1) {
    __shared__ float Ps[16][68];   // [k][i]
    __shared__ float Qs[16][68];   // [k][j]

    const int t  = threadIdx.x;        // 0..255
    const int tx = t & 15;
    const int ty = t >> 4;
    const int col0 = blockIdx.x * 64;
    const int row0 = blockIdx.y * 64;
    const bool isB = (col0 >= DDIM);
    const float* Wbase = W1 + (isB ? (size_t)(col0 - DDIM) * (2 * DDIM) + DDIM
                                   : (size_t)col0 * (2 * DDIM));

    const int lr  = t >> 2;            // 0..63
    const int lc4 = (t & 3) << 2;      // 0,4,8,12

    const float* Psrc = P + (size_t)(row0 + lr) * DDIM + lc4;
    const float* Wsrc = Wbase + (size_t)lr * (2 * DDIM) + lc4;

    float acc[4][4];
#pragma unroll
    for (int a = 0; a < 4; a++)
#pragma unroll
        for (int b = 0; b < 4; b++) acc[a][b] = 0.0f;

    // Prologue: prefetch chunk 0.
    float4 pv = *(const float4*)Psrc;
    float4 wv = *(const float4*)Wsrc;

    for (int k0 = 0; k0 < DDIM; k0 += 16) {
        // Store current chunk (transpose) to smem.
        Ps[lc4 + 0][lr] = pv.x; Ps[lc4 + 1][lr] = pv.y;
        Ps[lc4 + 2][lr] = pv.z; Ps[lc4 + 3][lr] = pv.w;
        Qs[lc4 + 0][lr] = wv.x; Qs[lc4 + 1][lr] = wv.y;
        Qs[lc4 + 2][lr] = wv.z; Qs[lc4 + 3][lr] = wv.w;
        __syncthreads();

        // Prefetch next chunk (latency hidden under compute below).
        if (k0 + 16 < DDIM) {
            pv = *(const float4*)(Psrc + k0 + 16);
            wv = *(const float4*)(Wsrc + k0 + 16);
        }

#pragma unroll
        for (int k = 0; k < 16; k++) {
            float4 av = *(const float4*)&Ps[k][ty << 2];
            float4 bv = *(const float4*)&Qs[k][tx << 2];
            float aa[4] = {av.x, av.y, av.z, av.w};
            float bb[4] = {bv.x, bv.y, bv.z, bv.w};
#pragma unroll
            for (int a = 0; a < 4; a++)
#pragma unroll
                for (int b = 0; b < 4; b++)
                    acc[a][b] = fmaf(aa[a], bb[b], acc[a][b]);
        }
        __syncthreads();
    }

    const int cbase = isB ? (col0 - DDIM) : col0;
    float* dst = isB ? g_B : g_A;
#pragma unroll
    for (int a = 0; a < 4; a++) {
        const int i = row0 + (ty << 2) + a;
#pragma unroll
        for (int b = 0; b < 4; b++) {
            const int j = cbase + (tx << 2) + b;
            float v = acc[a][b];
            if (!isB) v += b1[j];
            dst[(size_t)i * DDIM + j] = v;
        }
    }
}

// ---------------------------------------------------------------------------
// Phase 2: fused  out[i,j,c] = sum_d tanh(g_A[i,d] + g_B[j,d]) * W2[c,d] + b2[c]
// CTA tile: 16 i x 32 j, 512 threads. tz = t>>8 splits d in half (384 each);
// within a half: tx -> j = tx + 16*jj, ty -> i. d in smem chunks of 64,
// float2-vectorized. Row stride SP=70 -> LDS.64 conflict-free for 16 tx lanes.
// W2 preloaded once into a full smem strip (removed from the chunk loop).
// A/B chunk loads register-prefetched (zero LDG inside the steady-state loop).
// Grid (12, 24) = 288 CTAs -> 2 CTAs/SM, 32 warps/SM. MUFU.TANH floor ~25us.
// ---------------------------------------------------------------------------
#define TI 16
#define TJ 32
#define SP 70
#define DHALF 384

__global__ void __launch_bounds__(512, 2)
pair_kernel(const float* __restrict__ W2,
            const float* __restrict__ b2,
            float* __restrict__ out) {
    __shared__ float As[2][TI * SP];   // 8.96 KB
    __shared__ float Bs[2][TJ * SP];   // 17.9 KB
    __shared__ float W0a[DDIM];        // 3 KB
    __shared__ float W1a[DDIM];        // 3 KB
    __shared__ float Red[256 * 4];     // 4 KB

    const int t  = threadIdx.x;   // 0..511
    const int tz = t >> 8;        // d-half
    const int tt = t & 255;
    const int tx = tt & 15;
    const int ty = tt >> 4;
    const int i0 = blockIdx.y * TI;
    const int j0 = blockIdx.x * TJ;

    // One-time W2 strip preload: 1536 floats = 384 float4.
    if (t < 192) {
        *(float4*)&W0a[t << 2] = *(const float4*)(W2 + (t << 2));
    } else if (t < 384) {
        const int c4 = (t - 192) << 2;
        *(float4*)&W1a[c4] = *(const float4*)(W2 + DDIM + c4);
    }

    // Per-chunk load mapping: A row 0..15 (1 f4), B rows 0..15 and 16..31 (2 f4).
    const int lrow = tt >> 4;          // 0..15
    const int lc4  = (tt & 15) << 2;   // 0..60
    const float* Aptr  = g_A + (size_t)(i0 + lrow) * DDIM + tz * DHALF + lc4;
    const float* Bptr0 = g_B + (size_t)(j0 + lrow) * DDIM + tz * DHALF + lc4;
    const float* Bptr1 = g_B + (size_t)(j0 + 16 + lrow) * DDIM + tz * DHALF + lc4;

    float* Ash = As[tz];
    float* Bsh = Bs[tz];

    float acc0[2] = {0.f, 0.f};
    float acc1[2] = {0.f, 0.f};

    // Prologue: prefetch chunk 0 into registers.
    float4 av  = *(const float4*)Aptr;
    float4 bv0 = *(const float4*)Bptr0;
    float4 bv1 = *(const float4*)Bptr1;

    for (int c = 0; c < DHALF / 64; c++) {
        // Store current chunk to smem (float2 stores; SP rows are 8B-aligned).
        *(float2*)&Ash[lrow * SP + lc4]            = make_float2(av.x, av.y);
        *(float2*)&Ash[lrow * SP + lc4 + 2]        = make_float2(av.z, av.w);
        *(float2*)&Bsh[lrow * SP + lc4]            = make_float2(bv0.x, bv0.y);
        *(float2*)&Bsh[lrow * SP + lc4 + 2]        = make_float2(bv0.z, bv0.w);
        *(float2*)&Bsh[(16 + lrow) * SP + lc4]     = make_float2(bv1.x, bv1.y);
        *(float2*)&Bsh[(16 + lrow) * SP + lc4 + 2] = make_float2(bv1.z, bv1.w);
        __syncthreads();

        // Prefetch next chunk (hidden under the 32-iteration compute below).
        if (c + 1 < DHALF / 64) {
            const int off = (c + 1) * 64;
            av  = *(const float4*)(Aptr + off);
            bv0 = *(const float4*)(Bptr0 + off);
            bv1 = *(const float4*)(Bptr1 + off);
        }

        const float* Arow  = &Ash[ty * SP];
        const float* Brow0 = &Bsh[tx * SP];
        const float* Brow1 = &Bsh[(tx + 16) * SP];
        const float* W0h   = &W0a[tz * DHALF + c * 64];
        const float* W1h   = &W1a[tz * DHALF + c * 64];

#pragma unroll 8
        for (int dk = 0; dk < 64; dk += 2) {
            const float2 a2  = *(const float2*)&Arow[dk];
            const float2 w02 = *(const float2*)&W0h[dk];
            const float2 w12 = *(const float2*)&W1h[dk];

            {   // jj = 0
                const float2 bv = *(const float2*)&Brow0[dk];
                float th0, th1;
                asm("tanh.approx.f32 %0, %1;" : "=f"(th0) : "f"(a2.x + bv.x));
                asm("tanh.approx.f32 %0, %1;" : "=f"(th1) : "f"(a2.y + bv.y));
                acc0[0] = fmaf(th0, w02.x, acc0[0]);
                acc0[0] = fmaf(th1, w02.y, acc0[0]);
                acc1[0] = fmaf(th0, w12.x, acc1[0]);
                acc1[0] = fmaf(th1, w12.y, acc1[0]);
            }
            {   // jj = 1
                const float2 bv = *(const float2*)&Brow1[dk];
                float th0, th1;
                asm("tanh.approx.f32 %0, %1;" : "=f"(th0) : "f"(a2.x + bv.x));
                asm("tanh.approx.f32 %0, %1;" : "=f"(th1) : "f"(a2.y + bv.y));
                acc0[1] = fmaf(th0, w02.x, acc0[1]);
                acc0[1] = fmaf(th1, w02.y, acc0[1]);
                acc1[1] = fmaf(th0, w12.x, acc1[1]);
                acc1[1] = fmaf(th1, w12.y, acc1[1]);
            }
        }
        __syncthreads();
    }

    // Cross-half reduction: tz=1 parks its partials in smem, tz=0 combines.
    if (tz == 1) {
        *(float4*)&Red[tt * 4] = make_float4(acc0[0], acc0[1], acc1[0], acc1[1]);
    }
    __syncthreads();
    if (tz == 0) {
        float4 v = *(const float4*)&Red[tt * 4];
        const float bb0 = b2[0];
        const float bb1 = b2[1];
        const int i = i0 + ty;
        {
            const int j = j0 + tx;
            float2 o = make_float2(acc0[0] + v.x + bb0, acc1[0] + v.z + bb1);
            *(float2*)(out + ((size_t)i * NROWS + j) * 2) = o;
        }
        {
            const int j = j0 + tx + 16;
            float2 o = make_float2(acc0[1] + v.y + bb0, acc1[1] + v.w + bb1);
            *(float2*)(out + ((size_t)i * NROWS + j) * 2) = o;
        }
    }
}

// ---------------------------------------------------------------------------
extern "C" void kernel_launch(void* const* d_in, const int* in_sizes, int n_in,
                              void* d_out, int out_size) {
    const float* P  = (const float*)d_in[0];   // [384, 768]
    const float* W1 = (const float*)d_in[1];   // [768, 1536]
    const float* b1 = (const float*)d_in[2];   // [768]
    const float* W2 = (const float*)d_in[3];   // [2, 768]
    const float* b2 = (const float*)d_in[4];   // [2]
    float* out = (float*)d_out;                // [384, 384, 2]

    gemm_kernel<<<dim3(24, 6), 256>>>(P, W1, b1);
    pair_kernel<<<dim3(12, 24), 512>>>(W2, b2, out);
}

// round 6
// speedup vs baseline: 2.0216x; 1.0443x over previous
#include <cuda_runtime.h>
#include <cstdint>

#define NROWS 384
#define DDIM  768
#define KOFF  (NROWS * DDIM)   // element offset between split-k partial buffers

// Split-k partial outputs: g_A[z], g_B[z] for k-half z. Pair kernel sums them.
__device__ float g_A[2][NROWS * DDIM];
__device__ float g_B[2][NROWS * DDIM];

// ---------------------------------------------------------------------------
// Phase 1: split-k GEMM. C = P @ W1half^T. Grid (24, 6, 2): z = k-half.
// BM=BN=64, BK=16, 256 threads, 4x4 per thread, register-prefetch pipeline.
// 288 CTAs -> 2 CTAs/SM (barrier bubbles overlap between co-resident CTAs).
// b1 folded into the z=0 partial of g_A.
// ---------------------------------------------------------------------------
__global__ void __launch_bounds__(256)
gemm_kernel(const float* __restrict__ P,
            const float* __restrict__ W1,
            const float* __restrict__ b1) {
    __shared__ float Ps[16][68];   // [k][i]
    __shared__ float Qs[16][68];   // [k][j]

    const int t  = threadIdx.x;        // 0..255
    const int tx = t & 15;
    const int ty = t >> 4;
    const int col0 = blockIdx.x * 64;
    const int row0 = blockIdx.y * 64;
    const int z    = blockIdx.z;       // k-half
    const int koff = z * 384;
    const bool isB = (col0 >= DDIM);
    const float* Wbase = W1 + (isB ? (size_t)(col0 - DDIM) * (2 * DDIM) + DDIM
                                   : (size_t)col0 * (2 * DDIM));

    const int lr  = t >> 2;            // 0..63
    const int lc4 = (t & 3) << 2;      // 0,4,8,12

    const float* Psrc = P + (size_t)(row0 + lr) * DDIM + koff + lc4;
    const float* Wsrc = Wbase + (size_t)lr * (2 * DDIM) + koff + lc4;

    float acc[4][4];
#pragma unroll
    for (int a = 0; a < 4; a++)
#pragma unroll
        for (int b = 0; b < 4; b++) acc[a][b] = 0.0f;

    // Prologue: prefetch chunk 0.
    float4 pv = *(const float4*)Psrc;
    float4 wv = *(const float4*)Wsrc;

    for (int k0 = 0; k0 < 384; k0 += 16) {
        Ps[lc4 + 0][lr] = pv.x; Ps[lc4 + 1][lr] = pv.y;
        Ps[lc4 + 2][lr] = pv.z; Ps[lc4 + 3][lr] = pv.w;
        Qs[lc4 + 0][lr] = wv.x; Qs[lc4 + 1][lr] = wv.y;
        Qs[lc4 + 2][lr] = wv.z; Qs[lc4 + 3][lr] = wv.w;
        __syncthreads();

        if (k0 + 16 < 384) {
            pv = *(const float4*)(Psrc + k0 + 16);
            wv = *(const float4*)(Wsrc + k0 + 16);
        }

#pragma unroll
        for (int k = 0; k < 16; k++) {
            float4 av = *(const float4*)&Ps[k][ty << 2];
            float4 bv = *(const float4*)&Qs[k][tx << 2];
            float aa[4] = {av.x, av.y, av.z, av.w};
            float bb[4] = {bv.x, bv.y, bv.z, bv.w};
#pragma unroll
            for (int a = 0; a < 4; a++)
#pragma unroll
                for (int b = 0; b < 4; b++)
                    acc[a][b] = fmaf(aa[a], bb[b], acc[a][b]);
        }
        __syncthreads();
    }

    const int cbase = isB ? (col0 - DDIM) : col0;
    float* dst = (isB ? g_B[z] : g_A[z]);
    const int jc = cbase + (tx << 2);
    float4 badd = make_float4(0.f, 0.f, 0.f, 0.f);
    if (!isB && z == 0) badd = *(const float4*)(b1 + jc);
#pragma unroll
    for (int a = 0; a < 4; a++) {
        const int i = row0 + (ty << 2) + a;
        float4 v = make_float4(acc[a][0] + badd.x, acc[a][1] + badd.y,
                               acc[a][2] + badd.z, acc[a][3] + badd.w);
        *(float4*)(dst + (size_t)i * DDIM + jc) = v;
    }
}

// ---------------------------------------------------------------------------
// Phase 2: fused  out[i,j,c] = sum_d tanh(A[i,d] + B[j,d]) * W2[c,d] + b2[c]
// CTA tile 16i x 32j, 512 threads, d split into 4 quarters (tz, 128 thr each).
// Per-thread micro-tile 2i x 2j  ->  6 LDS.64 per 8 tanh (was 5 per 4):
// smem bandwidth per round 384cyc < MUFU 512cyc  ->  MUFU-bound.
// d chunks of 32 per quarter (6 chunks), smem row stride 34 (2k mod 32
// distinct -> conflict-free LDS.64). Split-k partials summed during prefetch
// via immediate-offset LDG. Grid (12,24)=288 -> 2 CTAs/SM, 8 warps/SMSP.
// ---------------------------------------------------------------------------
#define SPQ 34
#define DQ  192

__global__ void __launch_bounds__(512, 2)
pair_kernel(const float* __restrict__ W2,
            const float* __restrict__ b2,
            float* __restrict__ out) {
    __shared__ float As[4][16 * SPQ];   // 8.7 KB
    __shared__ float Bs[4][32 * SPQ];   // 17.4 KB
    __shared__ float W0a[DDIM];         // 3 KB
    __shared__ float W1a[DDIM];         // 3 KB
    __shared__ float Red[3 * 128 * 8];  // 12 KB

    const int t  = threadIdx.x;    // 0..511
    const int tz = t >> 7;         // d-quarter 0..3
    const int tt = t & 127;
    const int tx = tt & 15;        // j-group
    const int ty = tt >> 4;        // i-group 0..7
    const int i0 = blockIdx.y * 16;
    const int j0 = blockIdx.x * 32;

    // One-time W2 strip preload: 1536 floats = 384 float4.
    if (t < 192) {
        *(float4*)&W0a[t << 2] = *(const float4*)(W2 + (t << 2));
    } else if (t < 384) {
        const int c4 = (t - 192) << 2;
        *(float4*)&W1a[c4] = *(const float4*)(W2 + DDIM + c4);
    }

    // Per-chunk load mapping (within quarter): A 16x32 = 128 f4 (1/thread),
    // B 32x32 = 256 f4 (2/thread).
    const int lrow = tt >> 3;           // 0..15
    const int lc4  = (tt & 7) << 2;     // 0..28
    const float* Aptr  = g_A[0] + (size_t)(i0 + lrow) * DDIM + tz * DQ + lc4;
    const float* Bptr0 = g_B[0] + (size_t)(j0 + lrow) * DDIM + tz * DQ + lc4;
    const float* Bptr1 = g_B[0] + (size_t)(j0 + 16 + lrow) * DDIM + tz * DQ + lc4;

    float* Ash = As[tz];
    float* Bsh = Bs[tz];

    float acc0[2][2] = {{0.f, 0.f}, {0.f, 0.f}};   // [ii][jj] for class 0
    float acc1[2][2] = {{0.f, 0.f}, {0.f, 0.f}};   // [ii][jj] for class 1

    // Prologue: prefetch chunk 0, folding the two split-k partials.
    float4 av, bv0, bv1;
    {
        float4 x = *(const float4*)Aptr,          y = *(const float4*)(Aptr + KOFF);
        av  = make_float4(x.x + y.x, x.y + y.y, x.z + y.z, x.w + y.w);
        x = *(const float4*)Bptr0;  y = *(const float4*)(Bptr0 + KOFF);
        bv0 = make_float4(x.x + y.x, x.y + y.y, x.z + y.z, x.w + y.w);
        x = *(const float4*)Bptr1;  y = *(const float4*)(Bptr1 + KOFF);
        bv1 = make_float4(x.x + y.x, x.y + y.y, x.z + y.z, x.w + y.w);
    }

    for (int c = 0; c < DQ / 32; c++) {
        // Store current chunk (rows 8B-aligned -> float2 stores).
        *(float2*)&Ash[lrow * SPQ + lc4]            = make_float2(av.x, av.y);
        *(float2*)&Ash[lrow * SPQ + lc4 + 2]        = make_float2(av.z, av.w);
        *(float2*)&Bsh[lrow * SPQ + lc4]            = make_float2(bv0.x, bv0.y);
        *(float2*)&Bsh[lrow * SPQ + lc4 + 2]        = make_float2(bv0.z, bv0.w);
        *(float2*)&Bsh[(16 + lrow) * SPQ + lc4]     = make_float2(bv1.x, bv1.y);
        *(float2*)&Bsh[(16 + lrow) * SPQ + lc4 + 2] = make_float2(bv1.z, bv1.w);
        __syncthreads();

        // Prefetch next chunk (hidden under compute).
        if (c + 1 < DQ / 32) {
            const int off = (c + 1) * 32;
            float4 x = *(const float4*)(Aptr + off), y = *(const float4*)(Aptr + off + KOFF);
            av  = make_float4(x.x + y.x, x.y + y.y, x.z + y.z, x.w + y.w);
            x = *(const float4*)(Bptr0 + off);  y = *(const float4*)(Bptr0 + off + KOFF);
            bv0 = make_float4(x.x + y.x, x.y + y.y, x.z + y.z, x.w + y.w);
            x = *(const float4*)(Bptr1 + off);  y = *(const float4*)(Bptr1 + off + KOFF);
            bv1 = make_float4(x.x + y.x, x.y + y.y, x.z + y.z, x.w + y.w);
        }

        const float* Arow0 = &Ash[(2 * ty) * SPQ];
        const float* Arow1 = &Ash[(2 * ty + 1) * SPQ];
        const float* Brow0 = &Bsh[tx * SPQ];
        const float* Brow1 = &Bsh[(tx + 16) * SPQ];
        const float* W0h   = &W0a[tz * DQ + c * 32];
        const float* W1h   = &W1a[tz * DQ + c * 32];

#pragma unroll 8
        for (int dk = 0; dk < 32; dk += 2) {
            const float2 a0  = *(const float2*)&Arow0[dk];
            const float2 a1  = *(const float2*)&Arow1[dk];
            const float2 b0  = *(const float2*)&Brow0[dk];
            const float2 b1v = *(const float2*)&Brow1[dk];
            const float2 w0  = *(const float2*)&W0h[dk];
            const float2 w1  = *(const float2*)&W1h[dk];

            float th;
            // ii=0, jj=0
            asm("tanh.approx.f32 %0, %1;" : "=f"(th) : "f"(a0.x + b0.x));
            acc0[0][0] = fmaf(th, w0.x, acc0[0][0]);
            acc1[0][0] = fmaf(th, w1.x, acc1[0][0]);
            asm("tanh.approx.f32 %0, %1;" : "=f"(th) : "f"(a0.y + b0.y));
            acc0[0][0] = fmaf(th, w0.y, acc0[0][0]);
            acc1[0][0] = fmaf(th, w1.y, acc1[0][0]);
            // ii=0, jj=1
            asm("tanh.approx.f32 %0, %1;" : "=f"(th) : "f"(a0.x + b1v.x));
            acc0[0][1] = fmaf(th, w0.x, acc0[0][1]);
            acc1[0][1] = fmaf(th, w1.x, acc1[0][1]);
            asm("tanh.approx.f32 %0, %1;" : "=f"(th) : "f"(a0.y + b1v.y));
            acc0[0][1] = fmaf(th, w0.y, acc0[0][1]);
            acc1[0][1] = fmaf(th, w1.y, acc1[0][1]);
            // ii=1, jj=0
            asm("tanh.approx.f32 %0, %1;" : "=f"(th) : "f"(a1.x + b0.x));
            acc0[1][0] = fmaf(th, w0.x, acc0[1][0]);
            acc1[1][0] = fmaf(th, w1.x, acc1[1][0]);
            asm("tanh.approx.f32 %0, %1;" : "=f"(th) : "f"(a1.y + b0.y));
            acc0[1][0] = fmaf(th, w0.y, acc0[1][0]);
            acc1[1][0] = fmaf(th, w1.y, acc1[1][0]);
            // ii=1, jj=1
            asm("tanh.approx.f32 %0, %1;" : "=f"(th) : "f"(a1.x + b1v.x));
            acc0[1][1] = fmaf(th, w0.x, acc0[1][1]);
            acc1[1][1] = fmaf(th, w1.x, acc1[1][1]);
            asm("tanh.approx.f32 %0, %1;" : "=f"(th) : "f"(a1.y + b1v.y));
            acc0[1][1] = fmaf(th, w0.y, acc0[1][1]);
            acc1[1][1] = fmaf(th, w1.y, acc1[1][1]);
        }
        __syncthreads();
    }

    // Cross-quarter reduction: quarters 1..3 park 8 partials each, quarter 0 sums.
    if (tz > 0) {
        float* r = &Red[((tz - 1) * 128 + tt) * 8];
        *(float4*)r       = make_float4(acc0[0][0], acc0[0][1], acc0[1][0], acc0[1][1]);
        *(float4*)(r + 4) = make_float4(acc1[0][0], acc1[0][1], acc1[1][0], acc1[1][1]);
    }
    __syncthreads();
    if (tz == 0) {
#pragma unroll
        for (int q = 0; q < 3; q++) {
            const float* r = &Red[(q * 128 + tt) * 8];
            float4 p0 = *(const float4*)r;
            float4 p1 = *(const float4*)(r + 4);
            acc0[0][0] += p0.x; acc0[0][1] += p0.y; acc0[1][0] += p0.z; acc0[1][1] += p0.w;
            acc1[0][0] += p1.x; acc1[0][1] += p1.y; acc1[1][0] += p1.z; acc1[1][1] += p1.w;
        }
        const float bb0 = b2[0];
        const float bb1 = b2[1];
#pragma unroll
        for (int ii = 0; ii < 2; ii++) {
            const int i = i0 + 2 * ty + ii;
#pragma unroll
            for (int jj = 0; jj < 2; jj++) {
                const int j = j0 + tx + 16 * jj;
                float2 o = make_float2(acc0[ii][jj] + bb0, acc1[ii][jj] + bb1);
                *(float2*)(out + ((size_t)i * NROWS + j) * 2) = o;
            }
        }
    }
}

// ---------------------------------------------------------------------------
extern "C" void kernel_launch(void* const* d_in, const int* in_sizes, int n_in,
                              void* d_out, int out_size) {
    const float* P  = (const float*)d_in[0];   // [384, 768]
    const float* W1 = (const float*)d_in[1];   // [768, 1536]
    const float* b1 = (const float*)d_in[2];   // [768]
    const float* W2 = (const float*)d_in[3];   // [2, 768]
    const float* b2 = (const float*)d_in[4];   // [2]
    float* out = (float*)d_out;                // [384, 384, 2]

    gemm_kernel<<<dim3(24, 6, 2), 256>>>(P, W1, b1);
    pair_kernel<<<dim3(12, 24), 512>>>(W2, b2, out);
}